// round 11
// baseline (speedup 1.0000x reference)
#include <cuda_runtime.h>
#include <cuda_fp16.h>
#include <cstdint>

#define T_ 7
#define NTOK 36864            // B*H*W
#define ROWS (T_ * NTOK)      // 258048
#define CDIM 256
#define NQKV 768
#define NCTA 296              // 2 CTAs x 148 SMs
#define SBLKS 288             // NTOK/128
#define RBLKS 2016            // ROWS/128
#define ITEMS_PER_S 79        // 7 conv + 42 gemm1 + 16 attn + 14 gemm2
#define TOTAL_ITEMS (ITEMS_PER_S * SBLKS)   // 22752

// Scratch (device globals — no allocation allowed)
__device__ __half g_a_h[(size_t)ROWS * CDIM];    // frames, fp16
__device__ __half g_qkv_h[(size_t)ROWS * NQKV];  // [t*NTOK+s][q|k|v], fp16
__device__ __half g_ctx_h[(size_t)ROWS * CDIM];  // attn out, fp16
__device__ __half g_wbt_h[NQKV * CDIM];          // [n][k], fp16
__device__ __half g_wot_h[CDIM * CDIM];          // [c][nd], fp16
__device__ float  g_bias[T_ * NQKV];
// dependency flags (zeroed by prep each call)
__device__ int g_aconv[RBLKS];
__device__ int g_qkvr[SBLKS];
__device__ int g_ctxr[SBLKS];

// ---------------------------------------------------------------------------
// Portable PTX helpers (compute_103 virtual arch — no tcgen05/TMA-tensor)
// ---------------------------------------------------------------------------
__device__ __forceinline__ uint32_t smem_u32(const void* p) {
    uint32_t a;
    asm("{ .reg .u64 t; cvta.to.shared.u64 t, %1; cvt.u32.u64 %0, t; }" : "=r"(a) : "l"(p));
    return a;
}
__device__ __forceinline__ void ldsm4(uint32_t* r, uint32_t addr) {
    asm volatile("ldmatrix.sync.aligned.m8n8.x4.shared.b16 {%0,%1,%2,%3}, [%4];"
        : "=r"(r[0]), "=r"(r[1]), "=r"(r[2]), "=r"(r[3]) : "r"(addr));
}
__device__ __forceinline__ void mma_f16(float* d, const uint32_t* a, const uint32_t* b) {
    asm volatile("mma.sync.aligned.m16n8k16.row.col.f32.f16.f16.f32 "
        "{%0,%1,%2,%3}, {%4,%5,%6,%7}, {%8,%9}, {%0,%1,%2,%3};"
        : "+f"(d[0]), "+f"(d[1]), "+f"(d[2]), "+f"(d[3])
        : "r"(a[0]), "r"(a[1]), "r"(a[2]), "r"(a[3]), "r"(b[0]), "r"(b[1]));
}
#define CP_ASYNC16(dst, src) asm volatile("cp.async.cg.shared.global [%0], [%1], 16;" :: "r"(dst), "l"(src))
#define CP_COMMIT()          asm volatile("cp.async.commit_group;" ::: "memory")
#define CP_WAIT1()           asm volatile("cp.async.wait_group 1;" ::: "memory")
#define CP_WAIT0()           asm volatile("cp.async.wait_group 0;" ::: "memory")

__device__ __forceinline__ uint2 f4_to_h4(float4 v) {
    __half2 h0 = __float22half2_rn(make_float2(v.x, v.y));
    __half2 h1 = __float22half2_rn(make_float2(v.z, v.w));
    uint2 r;
    r.x = *reinterpret_cast<uint32_t*>(&h0);
    r.y = *reinterpret_cast<uint32_t*>(&h1);
    return r;
}
__device__ __forceinline__ float4 h4_to_f4(uint2 u) {
    __half2 h0 = *reinterpret_cast<__half2*>(&u.x);
    __half2 h1 = *reinterpret_cast<__half2*>(&u.y);
    float2 a = __half22float2(h0), b = __half22float2(h1);
    return make_float4(a.x, a.y, b.x, b.y);
}

#define STAGE_BYTES 32768u    // A 16KB (128x64 fp16) + B 16KB (128x64 fp16)
#define SM_TOTAL (3 * STAGE_BYTES)   // 96KB/CTA -> 2 CTAs/SM

// release: all threads fence, then one thread bumps the flag
__device__ __forceinline__ void signal_flag(int* f) {
    __threadfence();
    __syncthreads();
    if (threadIdx.x == 0) atomicAdd(f, 1);
}
// acquire: one thread spins, fence, CTA-wide sync
__device__ __forceinline__ void wait_flag(int* f, int target) {
    if (threadIdx.x == 0) {
        volatile int* vf = f;
        while (*vf < target) __nanosleep(128);
        __threadfence();
    }
    __syncthreads();
}

// ---------------------------------------------------------------------------
// Prep: weights pack+transpose, t_emb-folded bias, zero dependency flags.
// ---------------------------------------------------------------------------
#define NBLK_WT   1024        // (NQKV*CDIM + CDIM*CDIM)/256
#define NBLK_BIAS 21          // ceil(T_*NQKV/256)

__global__ void prep_kernel(const float* __restrict__ te,
                            const float* __restrict__ Wq,
                            const float* __restrict__ bq,
                            const float* __restrict__ Wk,
                            const float* __restrict__ bk,
                            const float* __restrict__ Wv,
                            const float* __restrict__ bv,
                            const float* __restrict__ Wo) {
    const int bid = blockIdx.x;
    if (bid < NBLK_WT) {
        int i = bid * 256 + threadIdx.x;
        if (i < NQKV * CDIM) {
            int n = i / CDIM, c = i % CDIM;
            float v;
            if (n < 256)      v = Wq[c * 256 + n];
            else if (n < 512) v = Wk[c * 256 + (n - 256)];
            else              v = Wv[c * 256 + (n - 512)];
            g_wbt_h[i] = __float2half_rn(v);
        } else {
            int j = i - NQKV * CDIM;
            int co = j / CDIM, nd = j % CDIM;
            g_wot_h[j] = __float2half_rn(Wo[nd * 256 + co]);
        }
    } else if (bid < NBLK_WT + NBLK_BIAS) {
        int i = (bid - NBLK_WT) * 256 + threadIdx.x;
        if (i >= T_ * NQKV) return;
        int t = i / NQKV, n = i % NQKV;
        float r;
        if (n < 512) {
            const float* W = (n < 256) ? Wq : Wk;
            int nn = n & 255;
            float acc = (n < 256) ? bq[nn] : bk[nn];
            for (int c = 0; c < CDIM; c++) acc += te[t * CDIM + c] * W[c * 256 + nn];
            r = acc;
        } else {
            r = bv[n - 512];
        }
        g_bias[i] = r;
    } else {
        // zero dependency flags
        for (int i = threadIdx.x; i < RBLKS; i += 256) g_aconv[i] = 0;
        for (int i = threadIdx.x; i < SBLKS; i += 256) { g_qkvr[i] = 0; g_ctxr[i] = 0; }
    }
}

// ---------------------------------------------------------------------------
// GEMM tile body (R8-proven): 128x128 tile, K=256 in 4 chunks, 3-stage ring,
// early next-stage issue, f32 smem epilogue + bias. NW runtime.
// ---------------------------------------------------------------------------
template<bool OUT_HALF>
__device__ __forceinline__ void gemm_tile(const __half* __restrict__ A,
                                          const __half* __restrict__ Bt,
                                          const float* __restrict__ biasrow,
                                          void* __restrict__ Cout, int NW,
                                          int row0, int col0,
                                          char* smem, uint32_t sb) {
    const int tid  = threadIdx.x;
    const int lane = tid & 31, wid = tid >> 5;
    const int wm = wid >> 1;          // 0..3 : rows wm*32
    const int wn = wid & 1;           // 0..1 : cols wn*64

    const uint32_t fxor  = (uint32_t)(lane & 7) << 4;
    const uint32_t a_row = (uint32_t)(wm * 32 + (lane & 15)) * 128;
    const uint32_t ahalf = (uint32_t)(lane >> 4) * 16;
    const uint32_t b_row = (uint32_t)(wn * 64 + (lane & 7) + ((lane >> 4) << 3)) * 128;
    const uint32_t bhalf = (uint32_t)((lane >> 3) & 1) * 16;

    auto stageA = [&](int kc, uint32_t nb) {
        #pragma unroll
        for (int i = 0; i < 4; i++) {
            int g = tid + i * 256;
            int r = g >> 3, c16 = g & 7;
            uint32_t dst = nb + (uint32_t)r * 128 + (((uint32_t)c16 * 16) ^ (((uint32_t)(r & 7)) << 4));
            CP_ASYNC16(dst, A + (size_t)(row0 + r) * CDIM + kc * 64 + c16 * 8);
        }
    };
    auto stageB = [&](int kc, uint32_t nb) {
        #pragma unroll
        for (int i = 0; i < 4; i++) {
            int g = tid + i * 256;
            int r = g >> 3, c16 = g & 7;
            uint32_t dst = nb + 16384u + (uint32_t)r * 128 + (((uint32_t)c16 * 16) ^ (((uint32_t)(r & 7)) << 4));
            CP_ASYNC16(dst, Bt + (size_t)(col0 + r) * CDIM + kc * 64 + c16 * 8);
        }
    };

    stageA(0, sb);               stageB(0, sb);               CP_COMMIT();
    stageA(1, sb + STAGE_BYTES); stageB(1, sb + STAGE_BYTES); CP_COMMIT();

    float acc[2][8][4];
    #pragma unroll
    for (int mt = 0; mt < 2; mt++)
        #pragma unroll
        for (int nt = 0; nt < 8; nt++)
            #pragma unroll
            for (int e = 0; e < 4; e++) acc[mt][nt][e] = 0.0f;

    #pragma unroll 1
    for (int kc = 0; kc < 4; kc++) {
        const uint32_t base = sb + (uint32_t)(kc % 3) * STAGE_BYTES;
        if (kc == 3) { CP_WAIT0(); } else { CP_WAIT1(); }
        __syncthreads();

        if (kc < 2) {
            const uint32_t nb = sb + (uint32_t)((kc + 2) % 3) * STAGE_BYTES;
            stageA(kc + 2, nb);
            stageB(kc + 2, nb);
            CP_COMMIT();
        }

        #pragma unroll
        for (int ks = 0; ks < 4; ks++) {
            uint32_t af[2][4];
            #pragma unroll
            for (int mt = 0; mt < 2; mt++)
                ldsm4(af[mt], base + a_row + (uint32_t)mt * 2048 + ((ahalf + ks * 32) ^ fxor));
            uint32_t bf[4][4];
            #pragma unroll
            for (int np = 0; np < 4; np++)
                ldsm4(bf[np], base + 16384u + b_row + (uint32_t)np * 2048 + ((bhalf + ks * 32) ^ fxor));
            #pragma unroll
            for (int mt = 0; mt < 2; mt++)
                #pragma unroll
                for (int nt = 0; nt < 8; nt++)
                    mma_f16(acc[mt][nt], af[mt], &bf[nt >> 1][(nt & 1) * 2]);
        }
    }
    __syncthreads();

    // epilogue: frags -> smem f32 -> coalesced global (+bias)
    float* Cs = reinterpret_cast<float*>(smem);    // [128][132] = 67.6KB (< 96KB ring)
    #pragma unroll
    for (int mt = 0; mt < 2; mt++) {
        const int r0 = wm * 32 + mt * 16 + (lane >> 2);
        #pragma unroll
        for (int nt = 0; nt < 8; nt++) {
            const int c0 = wn * 64 + nt * 8 + (lane & 3) * 2;
            *reinterpret_cast<float2*>(Cs + r0 * 132 + c0)       = make_float2(acc[mt][nt][0], acc[mt][nt][1]);
            *reinterpret_cast<float2*>(Cs + (r0 + 8) * 132 + c0) = make_float2(acc[mt][nt][2], acc[mt][nt][3]);
        }
    }
    __syncthreads();

    #pragma unroll
    for (int i = 0; i < 16; i++) {
        int id = tid + i * 256;                    // 4096 float4 slots
        int r = id >> 5, c = (id & 31) * 4;
        float4 v = *reinterpret_cast<const float4*>(Cs + r * 132 + c);
        int n = col0 + c;
        const float4 b4 = *reinterpret_cast<const float4*>(biasrow + n);
        v.x += b4.x; v.y += b4.y; v.z += b4.z; v.w += b4.w;
        if (OUT_HALF) {
            *reinterpret_cast<uint2*>(reinterpret_cast<__half*>(Cout) + (size_t)(row0 + r) * NW + n) = f4_to_h4(v);
        } else {
            *reinterpret_cast<float4*>(reinterpret_cast<float*>(Cout) + (size_t)(row0 + r) * NW + n) = v;
        }
    }
    __syncthreads();   // smem reuse fence before the CTA's next item
}

// ---------------------------------------------------------------------------
// Attention for 4 tokens (one pass): warp = (token, 4-head half).
// ---------------------------------------------------------------------------
__device__ __forceinline__ void attn_4tok(int s, int half, int lane) {
    const int hg = lane >> 3, dg = lane & 7;
    const int col = (half * 4 + hg) * 32 + dg * 4;

    float4 q[7], k[7], v[7];
    #pragma unroll
    for (int t = 0; t < 7; t++) {
        const __half* base = g_qkv_h + (size_t)(t * NTOK + s) * NQKV;
        q[t] = h4_to_f4(*reinterpret_cast<const uint2*>(base + col));
        k[t] = h4_to_f4(*reinterpret_cast<const uint2*>(base + 256 + col));
        v[t] = h4_to_f4(*reinterpret_cast<const uint2*>(base + 512 + col));
    }

    const float scale = 0.17677669529663687f;  // 1/sqrt(32)
    float e[7] = {0.f, 0.f, 0.f, 0.f, 0.f, 0.f, 0.f};
    #pragma unroll
    for (int qt = 0; qt < 7; qt++) {
        #pragma unroll
        for (int t = 0; t < 7; t++) {
            float d = q[qt].x * k[t].x + q[qt].y * k[t].y
                    + q[qt].z * k[t].z + q[qt].w * k[t].w;
            d += __shfl_xor_sync(0xffffffffu, d, 1);
            d += __shfl_xor_sync(0xffffffffu, d, 2);
            d += __shfl_xor_sync(0xffffffffu, d, 4);
            const int p = qt * 7 + t;
            if ((p & 7) == dg) e[p >> 3] = __expf(d * scale);
        }
    }

    float4 ctx[7];
    float den[7];
    #pragma unroll
    for (int qt = 0; qt < 7; qt++) { ctx[qt] = make_float4(0, 0, 0, 0); den[qt] = 0.f; }
    #pragma unroll
    for (int qt = 0; qt < 7; qt++) {
        #pragma unroll
        for (int t = 0; t < 7; t++) {
            const int p = qt * 7 + t;
            float eb = __shfl_sync(0xffffffffu, e[p >> 3], p & 7, 8);
            den[qt] += eb;
            ctx[qt].x += eb * v[t].x;
            ctx[qt].y += eb * v[t].y;
            ctx[qt].z += eb * v[t].z;
            ctx[qt].w += eb * v[t].w;
        }
    }
    #pragma unroll
    for (int qt = 0; qt < 7; qt++) {
        const float r = 1.0f / den[qt];
        float4 o = make_float4(ctx[qt].x * r, ctx[qt].y * r, ctx[qt].z * r, ctx[qt].w * r);
        *reinterpret_cast<uint2*>(g_ctx_h + (size_t)(qt * NTOK + s) * CDIM + col) = f4_to_h4(o);
    }
}

// ---------------------------------------------------------------------------
// Megakernel: statically-strided dependency-ordered work list.
// Per s-block: [7 conv][42 gemm1][16 attn][14 gemm2]. All dep edges point to
// strictly earlier items; CTA c runs items c, c+NCTA, ... (deadlock-free).
// ---------------------------------------------------------------------------
__global__ __launch_bounds__(256, 2)
void mega_kernel(const float* __restrict__ frames, float* __restrict__ out,
                 const float* __restrict__ bo) {
    extern __shared__ __align__(128) char smem[];
    const uint32_t sb = smem_u32(smem);
    const int tid = threadIdx.x;
    const int lane = tid & 31, wid = tid >> 5;

    #pragma unroll 1
    for (int item = blockIdx.x; item < TOTAL_ITEMS; item += NCTA) {
        const int sblk = item / ITEMS_PER_S;
        const int r = item - sblk * ITEMS_PER_S;

        if (r < 7) {
            // ---- conv: frames f32 -> fp16 for rowblk = r*288+sblk ----
            const int rowblk = r * SBLKS + sblk;
            const float4* src = reinterpret_cast<const float4*>(frames) + (size_t)rowblk * 128 * 64;
            uint2* dst = reinterpret_cast<uint2*>(g_a_h) + (size_t)rowblk * 128 * 64;
            #pragma unroll 8
            for (int i = 0; i < 32; i++) {
                int g = tid + i * 256;             // 8192 float4 slots
                dst[g] = f4_to_h4(src[g]);
            }
            signal_flag(&g_aconv[rowblk]);
        } else if (r < 49) {
            // ---- GEMM1 tile ----
            const int q = r - 7;
            const int t = q / 6, col = q % 6;
            const int rowblk = t * SBLKS + sblk;
            wait_flag(&g_aconv[rowblk], 1);
            gemm_tile<true>(g_a_h, g_wbt_h, g_bias + t * NQKV,
                            (void*)g_qkv_h, NQKV, rowblk * 128, col * 128, smem, sb);
            signal_flag(&g_qkvr[sblk]);
        } else if (r < 65) {
            // ---- attention: 8 tokens (2 passes of 4) ----
            wait_flag(&g_qkvr[sblk], 42);
            const int a = r - 49;
            #pragma unroll
            for (int pass = 0; pass < 2; pass++) {
                const int s = sblk * 128 + a * 8 + pass * 4 + (wid >> 1);
                attn_4tok(s, wid & 1, lane);
            }
            signal_flag(&g_ctxr[sblk]);
        } else {
            // ---- GEMM2 tile ----
            const int g = r - 65;
            const int t = g >> 1, col = g & 1;
            wait_flag(&g_ctxr[sblk], 16);
            gemm_tile<false>(g_ctx_h, g_wot_h, bo,
                             (void*)out, CDIM, (t * SBLKS + sblk) * 128, col * 128, smem, sb);
        }
    }
}

// ---------------------------------------------------------------------------
extern "C" void kernel_launch(void* const* d_in, const int* /*in_sizes*/, int /*n_in*/,
                              void* d_out, int /*out_size*/) {
    const float* frames = (const float*)d_in[0];
    const float* temb   = (const float*)d_in[1];
    const float* Wq     = (const float*)d_in[2];
    const float* bq     = (const float*)d_in[3];
    const float* Wk     = (const float*)d_in[4];
    const float* bk     = (const float*)d_in[5];
    const float* Wv     = (const float*)d_in[6];
    const float* bv     = (const float*)d_in[7];
    const float* Wo     = (const float*)d_in[8];
    const float* bo     = (const float*)d_in[9];
    float* out = (float*)d_out;

    cudaFuncSetAttribute(mega_kernel,
                         cudaFuncAttributeMaxDynamicSharedMemorySize, SM_TOTAL);

    // Prep: weight pack + bias fold + flag zeroing
    prep_kernel<<<NBLK_WT + NBLK_BIAS + 1, 256>>>(temb, Wq, bq, Wk, bk, Wv, bv, Wo);

    // Fused conv + QKV GEMM + attention + output GEMM
    mega_kernel<<<NCTA, 256, SM_TOTAL>>>(frames, out, bo);
}

// round 12
// speedup vs baseline: 2.4077x; 2.4077x over previous
#include <cuda_runtime.h>
#include <cuda_fp16.h>
#include <cstdint>

#define T_ 7
#define NTOK 36864            // B*H*W
#define ROWS (T_ * NTOK)      // 258048
#define CDIM 256
#define NQKV 768
#define NCTA 296              // 2 CTAs x 148 SMs

// Scratch (device globals — no allocation allowed)
__device__ __half g_a_h[(size_t)ROWS * CDIM];    // frames, fp16
__device__ __half g_qkv_h[(size_t)ROWS * NQKV];  // [t*NTOK+s][q|k|v], fp16
__device__ __half g_ctx_h[(size_t)ROWS * CDIM];  // attn out, fp16
__device__ __half g_wbt_h[NQKV * CDIM];          // [n][k], fp16
__device__ __half g_wot_h[CDIM * CDIM];          // [c][nd], fp16
__device__ float  g_bias[T_ * NQKV];

// ---------------------------------------------------------------------------
// Portable PTX helpers (compute_103 virtual arch — no tcgen05/TMA-tensor)
// ---------------------------------------------------------------------------
__device__ __forceinline__ uint32_t smem_u32(const void* p) {
    uint32_t a;
    asm("{ .reg .u64 t; cvta.to.shared.u64 t, %1; cvt.u32.u64 %0, t; }" : "=r"(a) : "l"(p));
    return a;
}
__device__ __forceinline__ void ldsm4(uint32_t* r, uint32_t addr) {
    asm volatile("ldmatrix.sync.aligned.m8n8.x4.shared.b16 {%0,%1,%2,%3}, [%4];"
        : "=r"(r[0]), "=r"(r[1]), "=r"(r[2]), "=r"(r[3]) : "r"(addr));
}
__device__ __forceinline__ void mma_f16(float* d, const uint32_t* a, const uint32_t* b) {
    asm volatile("mma.sync.aligned.m16n8k16.row.col.f32.f16.f16.f32 "
        "{%0,%1,%2,%3}, {%4,%5,%6,%7}, {%8,%9}, {%0,%1,%2,%3};"
        : "+f"(d[0]), "+f"(d[1]), "+f"(d[2]), "+f"(d[3])
        : "r"(a[0]), "r"(a[1]), "r"(a[2]), "r"(a[3]), "r"(b[0]), "r"(b[1]));
}
#define CP_ASYNC16(dst, src) asm volatile("cp.async.cg.shared.global [%0], [%1], 16;" :: "r"(dst), "l"(src))
#define CP_COMMIT()          asm volatile("cp.async.commit_group;" ::: "memory")
#define CP_WAIT1()           asm volatile("cp.async.wait_group 1;" ::: "memory")
#define CP_WAIT0()           asm volatile("cp.async.wait_group 0;" ::: "memory")

__device__ __forceinline__ uint2 f4_to_h4(float4 v) {
    __half2 h0 = __float22half2_rn(make_float2(v.x, v.y));
    __half2 h1 = __float22half2_rn(make_float2(v.z, v.w));
    uint2 r;
    r.x = *reinterpret_cast<uint32_t*>(&h0);
    r.y = *reinterpret_cast<uint32_t*>(&h1);
    return r;
}
__device__ __forceinline__ float4 h4_to_f4(uint2 u) {
    __half2 h0 = *reinterpret_cast<__half2*>(&u.x);
    __half2 h1 = *reinterpret_cast<__half2*>(&u.y);
    float2 a = __half22float2(h0), b = __half22float2(h1);
    return make_float4(a.x, a.y, b.x, b.y);
}

#define STAGE_BYTES 32768u    // A 16KB (128x64 fp16) + B 16KB (128x64 fp16)
#define SM_TOTAL (3 * STAGE_BYTES)   // 96KB/CTA -> 2 CTAs/SM

// ---------------------------------------------------------------------------
// Merged prep: frames f32->fp16, weights pack+transpose, t_emb-folded bias.
// ---------------------------------------------------------------------------
#define NBLK_FRAMES 64512     // ROWS*CDIM/4/256
#define NBLK_WT     1024      // (NQKV*CDIM + CDIM*CDIM)/256
#define NBLK_BIAS   21        // ceil(T_*NQKV/256)

__global__ void prep_all_kernel(const float* __restrict__ frames,
                                const float* __restrict__ te,
                                const float* __restrict__ Wq,
                                const float* __restrict__ bq,
                                const float* __restrict__ Wk,
                                const float* __restrict__ bk,
                                const float* __restrict__ Wv,
                                const float* __restrict__ bv,
                                const float* __restrict__ Wo) {
    const int bid = blockIdx.x;
    if (bid < NBLK_FRAMES) {
        size_t i = (size_t)bid * 256 + threadIdx.x;     // float4 slot
        const float4 v = reinterpret_cast<const float4*>(frames)[i];
        reinterpret_cast<uint2*>(g_a_h)[i] = f4_to_h4(v);
    } else if (bid < NBLK_FRAMES + NBLK_WT) {
        int i = (bid - NBLK_FRAMES) * 256 + threadIdx.x;
        if (i < NQKV * CDIM) {
            int n = i / CDIM, c = i % CDIM;
            float v;
            if (n < 256)      v = Wq[c * 256 + n];
            else if (n < 512) v = Wk[c * 256 + (n - 256)];
            else              v = Wv[c * 256 + (n - 512)];
            g_wbt_h[i] = __float2half_rn(v);
        } else {
            int j = i - NQKV * CDIM;
            int co = j / CDIM, nd = j % CDIM;
            g_wot_h[j] = __float2half_rn(Wo[nd * 256 + co]);
        }
    } else {
        int i = (bid - NBLK_FRAMES - NBLK_WT) * 256 + threadIdx.x;
        if (i >= T_ * NQKV) return;
        int t = i / NQKV, n = i % NQKV;
        float r;
        if (n < 512) {
            const float* W = (n < 256) ? Wq : Wk;
            int nn = n & 255;
            float acc = (n < 256) ? bq[nn] : bk[nn];
            for (int c = 0; c < CDIM; c++) acc += te[t * CDIM + c] * W[c * 256 + nn];
            r = acc;
        } else {
            r = bv[n - 512];
        }
        g_bias[i] = r;
    }
}

// ---------------------------------------------------------------------------
// fp16 mma.sync GEMM (R8-proven): C[row][n] = A[row][k] * Bt[n][k] + bias
// CTA 128(M) x 128(N), K=256 in 4 chunks of 64, 3-stage cp.async pipeline,
// next-stage issued BEFORE compute. 8 warps, warp tile 32x64.
// __launch_bounds__(256,2): 2 CTAs/SM.
// ---------------------------------------------------------------------------
template<int NW, int TSTRIDE, bool OUT_HALF>
__global__ __launch_bounds__(256, 2)
void gemm_h_kernel(const __half* __restrict__ A,
                   const __half* __restrict__ Bt,
                   const float* __restrict__ bias,
                   void* __restrict__ Cout) {
    extern __shared__ __align__(128) char smem[];
    const uint32_t sb = smem_u32(smem);

    const int tid  = threadIdx.x;
    const int lane = tid & 31, wid = tid >> 5;
    const int wm = wid >> 1;          // 0..3 : rows wm*32
    const int wn = wid & 1;           // 0..1 : cols wn*64
    const int row0 = blockIdx.y * 128;
    const int col0 = blockIdx.x * 128;

    const uint32_t fxor  = (uint32_t)(lane & 7) << 4;
    const uint32_t a_row = (uint32_t)(wm * 32 + (lane & 15)) * 128;
    const uint32_t ahalf = (uint32_t)(lane >> 4) * 16;
    const uint32_t b_row = (uint32_t)(wn * 64 + (lane & 7) + ((lane >> 4) << 3)) * 128;
    const uint32_t bhalf = (uint32_t)((lane >> 3) & 1) * 16;

    auto stageA = [&](int kc, uint32_t nb) {
        #pragma unroll
        for (int i = 0; i < 4; i++) {
            int g = tid + i * 256;
            int r = g >> 3, c16 = g & 7;
            uint32_t dst = nb + (uint32_t)r * 128 + (((uint32_t)c16 * 16) ^ (((uint32_t)(r & 7)) << 4));
            CP_ASYNC16(dst, A + (size_t)(row0 + r) * CDIM + kc * 64 + c16 * 8);
        }
    };
    auto stageB = [&](int kc, uint32_t nb) {
        #pragma unroll
        for (int i = 0; i < 4; i++) {
            int g = tid + i * 256;
            int r = g >> 3, c16 = g & 7;
            uint32_t dst = nb + 16384u + (uint32_t)r * 128 + (((uint32_t)c16 * 16) ^ (((uint32_t)(r & 7)) << 4));
            CP_ASYNC16(dst, Bt + (size_t)(col0 + r) * CDIM + kc * 64 + c16 * 8);
        }
    };

    stageA(0, sb);               stageB(0, sb);               CP_COMMIT();
    stageA(1, sb + STAGE_BYTES); stageB(1, sb + STAGE_BYTES); CP_COMMIT();

    float acc[2][8][4];
    #pragma unroll
    for (int mt = 0; mt < 2; mt++)
        #pragma unroll
        for (int nt = 0; nt < 8; nt++)
            #pragma unroll
            for (int e = 0; e < 4; e++) acc[mt][nt][e] = 0.0f;

    #pragma unroll 1
    for (int kc = 0; kc < 4; kc++) {
        const uint32_t sbase = sb + (uint32_t)(kc % 3) * STAGE_BYTES;
        if (kc == 3) { CP_WAIT0(); } else { CP_WAIT1(); }
        __syncthreads();

        if (kc < 2) {
            const uint32_t nb = sb + (uint32_t)((kc + 2) % 3) * STAGE_BYTES;
            stageA(kc + 2, nb);
            stageB(kc + 2, nb);
            CP_COMMIT();
        }

        #pragma unroll
        for (int ks = 0; ks < 4; ks++) {
            uint32_t af[2][4];
            #pragma unroll
            for (int mt = 0; mt < 2; mt++)
                ldsm4(af[mt], sbase + a_row + (uint32_t)mt * 2048 + ((ahalf + ks * 32) ^ fxor));
            uint32_t bf[4][4];
            #pragma unroll
            for (int np = 0; np < 4; np++)
                ldsm4(bf[np], sbase + 16384u + b_row + (uint32_t)np * 2048 + ((bhalf + ks * 32) ^ fxor));
            #pragma unroll
            for (int mt = 0; mt < 2; mt++)
                #pragma unroll
                for (int nt = 0; nt < 8; nt++)
                    mma_f16(acc[mt][nt], af[mt], &bf[nt >> 1][(nt & 1) * 2]);
        }
    }
    __syncthreads();

    float* Cs = reinterpret_cast<float*>(smem);    // [128][132] = 67.6KB
    #pragma unroll
    for (int mt = 0; mt < 2; mt++) {
        const int r0 = wm * 32 + mt * 16 + (lane >> 2);
        #pragma unroll
        for (int nt = 0; nt < 8; nt++) {
            const int c0 = wn * 64 + nt * 8 + (lane & 3) * 2;
            *reinterpret_cast<float2*>(Cs + r0 * 132 + c0)       = make_float2(acc[mt][nt][0], acc[mt][nt][1]);
            *reinterpret_cast<float2*>(Cs + (r0 + 8) * 132 + c0) = make_float2(acc[mt][nt][2], acc[mt][nt][3]);
        }
    }
    __syncthreads();

    const int t = TSTRIDE ? (blockIdx.y / 288) : 0;
    #pragma unroll
    for (int i = 0; i < 16; i++) {
        int id = tid + i * 256;                    // 4096 float4 slots
        int r = id >> 5, c = (id & 31) * 4;
        float4 v = *reinterpret_cast<const float4*>(Cs + r * 132 + c);
        int n = col0 + c;
        const float4 b4 = *reinterpret_cast<const float4*>(bias + t * TSTRIDE + n);
        v.x += b4.x; v.y += b4.y; v.z += b4.z; v.w += b4.w;
        if (OUT_HALF) {
            *reinterpret_cast<uint2*>(reinterpret_cast<__half*>(Cout) + (size_t)(row0 + r) * NW + n) = f4_to_h4(v);
        } else {
            *reinterpret_cast<float4*>(reinterpret_cast<float*>(Cout) + (size_t)(row0 + r) * NW + n) = v;
        }
    }
}

// ---------------------------------------------------------------------------
// Persistent GEMM2 (measured 119.6us in R10 vs 125us grid version).
// 296 CTAs; continuous 3-buffer ring across tiles; epilogue via freed buffer.
// ---------------------------------------------------------------------------
template<int NB, int TSTRIDE, bool OUT_HALF>
__global__ __launch_bounds__(256, 2)
void gemm_persist_kernel(const __half* __restrict__ A,
                         const __half* __restrict__ Bt,
                         const float* __restrict__ bias,
                         void* __restrict__ Cout) {
    extern __shared__ __align__(128) char smem[];
    const uint32_t sb = smem_u32(smem);
    const int NWIDTH = NB * 128;
    const int ntiles = NB * (ROWS / 128);

    const int tid  = threadIdx.x;
    const int lane = tid & 31, wid = tid >> 5;
    const int wm = wid >> 1;
    const int wn = wid & 1;
    const int cblk = blockIdx.x;

    const uint32_t fxor  = (uint32_t)(lane & 7) << 4;
    const uint32_t a_row = (uint32_t)(wm * 32 + (lane & 15)) * 128;
    const uint32_t ahalf = (uint32_t)(lane >> 4) * 16;
    const uint32_t b_row = (uint32_t)(wn * 64 + (lane & 7) + ((lane >> 4) << 3)) * 128;
    const uint32_t bhalf = (uint32_t)((lane >> 3) & 1) * 16;

    auto stageG = [&](int gl) {
        const int tt = cblk + (gl >> 2) * NCTA;
        if (tt < ntiles) {
            const int kc = gl & 3;
            const int r0 = (tt / NB) * 128;
            const int c0 = (tt % NB) * 128;
            const uint32_t nb = sb + (uint32_t)(gl % 3) * STAGE_BYTES;
            #pragma unroll
            for (int i = 0; i < 4; i++) {
                int g = tid + i * 256;
                int r = g >> 3, c16 = g & 7;
                uint32_t dst = nb + (uint32_t)r * 128 + (((uint32_t)c16 * 16) ^ (((uint32_t)(r & 7)) << 4));
                CP_ASYNC16(dst, A + (size_t)(r0 + r) * CDIM + kc * 64 + c16 * 8);
            }
            #pragma unroll
            for (int i = 0; i < 4; i++) {
                int g = tid + i * 256;
                int r = g >> 3, c16 = g & 7;
                uint32_t dst = nb + 16384u + (uint32_t)r * 128 + (((uint32_t)c16 * 16) ^ (((uint32_t)(r & 7)) << 4));
                CP_ASYNC16(dst, Bt + (size_t)(c0 + r) * CDIM + kc * 64 + c16 * 8);
            }
        }
        CP_COMMIT();
    };

    stageG(0);
    stageG(1);

    int gl = 0;
    #pragma unroll 1
    for (int tau = cblk; tau < ntiles; tau += NCTA) {
        const int rowblk = tau / NB;
        const int row0 = rowblk * 128;
        const int col0 = (tau % NB) * 128;

        float acc[2][8][4];
        #pragma unroll
        for (int mt = 0; mt < 2; mt++)
            #pragma unroll
            for (int nt = 0; nt < 8; nt++)
                #pragma unroll
                for (int e = 0; e < 4; e++) acc[mt][nt][e] = 0.0f;

        #pragma unroll 1
        for (int kc = 0; kc < 4; kc++, gl++) {
            const uint32_t base = sb + (uint32_t)(gl % 3) * STAGE_BYTES;
            CP_WAIT1();
            __syncthreads();
            stageG(gl + 2);

            #pragma unroll
            for (int ks = 0; ks < 4; ks++) {
                uint32_t af[2][4];
                #pragma unroll
                for (int mt = 0; mt < 2; mt++)
                    ldsm4(af[mt], base + a_row + (uint32_t)mt * 2048 + ((ahalf + ks * 32) ^ fxor));
                uint32_t bf[4][4];
                #pragma unroll
                for (int np = 0; np < 4; np++)
                    ldsm4(bf[np], base + 16384u + b_row + (uint32_t)np * 2048 + ((bhalf + ks * 32) ^ fxor));
                #pragma unroll
                for (int mt = 0; mt < 2; mt++)
                    #pragma unroll
                    for (int nt = 0; nt < 8; nt++)
                        mma_f16(acc[mt][nt], af[mt], &bf[nt >> 1][(nt & 1) * 2]);
            }
        }
        __syncthreads();

        float* Cs = reinterpret_cast<float*>(smem + (size_t)((gl + 2) % 3) * STAGE_BYTES);
        const int t = TSTRIDE ? (rowblk / 288) : 0;

        #pragma unroll 1
        for (int p = 0; p < 4; p++) {
            if (wm == p) {
                #pragma unroll
                for (int mt = 0; mt < 2; mt++) {
                    const int r0 = mt * 16 + (lane >> 2);
                    #pragma unroll
                    for (int nt = 0; nt < 8; nt++) {
                        const int c0 = wn * 64 + nt * 8 + (lane & 3) * 2;
                        *reinterpret_cast<float2*>(Cs + r0 * 132 + c0)       = make_float2(acc[mt][nt][0], acc[mt][nt][1]);
                        *reinterpret_cast<float2*>(Cs + (r0 + 8) * 132 + c0) = make_float2(acc[mt][nt][2], acc[mt][nt][3]);
                    }
                }
            }
            __syncthreads();
            #pragma unroll
            for (int i = 0; i < 4; i++) {
                int id = tid + i * 256;
                int r = id >> 5, c = (id & 31) * 4;
                float4 v = *reinterpret_cast<const float4*>(Cs + r * 132 + c);
                int n = col0 + c;
                const float4 b4 = *reinterpret_cast<const float4*>(bias + t * TSTRIDE + n);
                v.x += b4.x; v.y += b4.y; v.z += b4.z; v.w += b4.w;
                const size_t grow = (size_t)(row0 + p * 32 + r);
                if (OUT_HALF) {
                    *reinterpret_cast<uint2*>(reinterpret_cast<__half*>(Cout) + grow * NWIDTH + n) = f4_to_h4(v);
                } else {
                    *reinterpret_cast<float4*>(reinterpret_cast<float*>(Cout) + grow * NWIDTH + n) = v;
                }
            }
            __syncthreads();
        }
    }
}

// ---------------------------------------------------------------------------
// Attention over T=7 per (token, 4-head group), fp16 in / fp16 out.
// ---------------------------------------------------------------------------
__global__ void attn_kernel() {
    const int gw = (blockIdx.x * blockDim.x + threadIdx.x) >> 5;
    const int lane = threadIdx.x & 31;
    const int s = gw >> 1;
    const int half = gw & 1;
    const int hg = lane >> 3, dg = lane & 7;
    const int col = (half * 4 + hg) * 32 + dg * 4;

    float4 q[7], k[7], v[7];
    #pragma unroll
    for (int t = 0; t < 7; t++) {
        const __half* base = g_qkv_h + (size_t)(t * NTOK + s) * NQKV;
        q[t] = h4_to_f4(*reinterpret_cast<const uint2*>(base + col));
        k[t] = h4_to_f4(*reinterpret_cast<const uint2*>(base + 256 + col));
        v[t] = h4_to_f4(*reinterpret_cast<const uint2*>(base + 512 + col));
    }

    const float scale = 0.17677669529663687f;  // 1/sqrt(32)
    float e[7] = {0.f, 0.f, 0.f, 0.f, 0.f, 0.f, 0.f};
    #pragma unroll
    for (int qt = 0; qt < 7; qt++) {
        #pragma unroll
        for (int t = 0; t < 7; t++) {
            float d = q[qt].x * k[t].x + q[qt].y * k[t].y
                    + q[qt].z * k[t].z + q[qt].w * k[t].w;
            d += __shfl_xor_sync(0xffffffffu, d, 1);
            d += __shfl_xor_sync(0xffffffffu, d, 2);
            d += __shfl_xor_sync(0xffffffffu, d, 4);
            const int p = qt * 7 + t;
            if ((p & 7) == dg) e[p >> 3] = __expf(d * scale);
        }
    }

    float4 ctx[7];
    float den[7];
    #pragma unroll
    for (int qt = 0; qt < 7; qt++) { ctx[qt] = make_float4(0, 0, 0, 0); den[qt] = 0.f; }
    #pragma unroll
    for (int qt = 0; qt < 7; qt++) {
        #pragma unroll
        for (int t = 0; t < 7; t++) {
            const int p = qt * 7 + t;
            float eb = __shfl_sync(0xffffffffu, e[p >> 3], p & 7, 8);
            den[qt] += eb;
            ctx[qt].x += eb * v[t].x;
            ctx[qt].y += eb * v[t].y;
            ctx[qt].z += eb * v[t].z;
            ctx[qt].w += eb * v[t].w;
        }
    }
    #pragma unroll
    for (int qt = 0; qt < 7; qt++) {
        const float r = 1.0f / den[qt];
        float4 o = make_float4(ctx[qt].x * r, ctx[qt].y * r, ctx[qt].z * r, ctx[qt].w * r);
        *reinterpret_cast<uint2*>(g_ctx_h + (size_t)(qt * NTOK + s) * CDIM + col) = f4_to_h4(o);
    }
}

// ---------------------------------------------------------------------------
extern "C" void kernel_launch(void* const* d_in, const int* /*in_sizes*/, int /*n_in*/,
                              void* d_out, int /*out_size*/) {
    const float* frames = (const float*)d_in[0];
    const float* temb   = (const float*)d_in[1];
    const float* Wq     = (const float*)d_in[2];
    const float* bq     = (const float*)d_in[3];
    const float* Wk     = (const float*)d_in[4];
    const float* bk     = (const float*)d_in[5];
    const float* Wv     = (const float*)d_in[6];
    const float* bv     = (const float*)d_in[7];
    const float* Wo     = (const float*)d_in[8];
    const float* bo     = (const float*)d_in[9];
    float* out = (float*)d_out;

    void *p_ah, *p_qkv, *p_ctx, *p_wbt, *p_wot, *p_bias;
    cudaGetSymbolAddress(&p_ah,   g_a_h);
    cudaGetSymbolAddress(&p_qkv,  g_qkv_h);
    cudaGetSymbolAddress(&p_ctx,  g_ctx_h);
    cudaGetSymbolAddress(&p_wbt,  g_wbt_h);
    cudaGetSymbolAddress(&p_wot,  g_wot_h);
    cudaGetSymbolAddress(&p_bias, g_bias);

    cudaFuncSetAttribute(gemm_h_kernel<NQKV, NQKV, true>,
                         cudaFuncAttributeMaxDynamicSharedMemorySize, SM_TOTAL);
    cudaFuncSetAttribute(gemm_persist_kernel<2, 0, false>,
                         cudaFuncAttributeMaxDynamicSharedMemorySize, SM_TOTAL);

    // Single prep launch: frames->fp16, weight pack, bias fold
    prep_all_kernel<<<NBLK_FRAMES + NBLK_WT + NBLK_BIAS, 256>>>(
        frames, temb, Wq, bq, Wk, bk, Wv, bv, Wo);

    // QKV projection: [258048 x 256] @ [256 x 768] + bias[t]  -> fp16 qkv
    gemm_h_kernel<NQKV, NQKV, true><<<dim3(6, ROWS / 128), 256, SM_TOTAL>>>(
        (const __half*)p_ah, (const __half*)p_wbt, (const float*)p_bias, p_qkv);

    // Attention (fp16 -> fp16)
    attn_kernel<<<(NTOK * 2 * 32) / 256, 256>>>();

    // Output projection (persistent): [258048 x 256] @ [256 x 256] + bo -> f32 out
    gemm_persist_kernel<2, 0, false><<<NCTA, 256, SM_TOTAL>>>(
        (const __half*)p_ctx, (const __half*)p_wot, bo, (void*)out);
}

// round 14
// speedup vs baseline: 2.6153x; 1.0862x over previous
#include <cuda_runtime.h>
#include <cuda_fp16.h>
#include <cstdint>

#define T_ 7
#define NTOK 36864            // B*H*W
#define ROWS (T_ * NTOK)      // 258048
#define CDIM 256
#define NQKV 768

// Scratch (device globals — no allocation allowed)
__device__ __half g_a_h[(size_t)ROWS * CDIM];    // frames, fp16
__device__ __half g_qkv_h[(size_t)ROWS * NQKV];  // [t*NTOK+s][q|k|v], fp16
__device__ __half g_ctx_h[(size_t)ROWS * CDIM];  // attn out, fp16
__device__ __half g_wbt_h[NQKV * CDIM];          // [n][k], fp16
__device__ __half g_wot_h[CDIM * CDIM];          // [c][nd], fp16
__device__ float  g_bias[T_ * NQKV];

// ---------------------------------------------------------------------------
// Portable PTX helpers (compute_103 virtual arch — no tcgen05/TMA-tensor)
// ---------------------------------------------------------------------------
__device__ __forceinline__ uint32_t smem_u32(const void* p) {
    uint32_t a;
    asm("{ .reg .u64 t; cvta.to.shared.u64 t, %1; cvt.u32.u64 %0, t; }" : "=r"(a) : "l"(p));
    return a;
}
__device__ __forceinline__ void ldsm4(uint32_t* r, uint32_t addr) {
    asm volatile("ldmatrix.sync.aligned.m8n8.x4.shared.b16 {%0,%1,%2,%3}, [%4];"
        : "=r"(r[0]), "=r"(r[1]), "=r"(r[2]), "=r"(r[3]) : "r"(addr));
}
__device__ __forceinline__ void mma_f16(float* d, const uint32_t* a, const uint32_t* b) {
    asm volatile("mma.sync.aligned.m16n8k16.row.col.f32.f16.f16.f32 "
        "{%0,%1,%2,%3}, {%4,%5,%6,%7}, {%8,%9}, {%0,%1,%2,%3};"
        : "+f"(d[0]), "+f"(d[1]), "+f"(d[2]), "+f"(d[3])
        : "r"(a[0]), "r"(a[1]), "r"(a[2]), "r"(a[3]), "r"(b[0]), "r"(b[1]));
}
#define CP_ASYNC16(dst, src) asm volatile("cp.async.cg.shared.global [%0], [%1], 16;" :: "r"(dst), "l"(src))
#define CP_COMMIT()          asm volatile("cp.async.commit_group;" ::: "memory")
#define CP_WAIT1()           asm volatile("cp.async.wait_group 1;" ::: "memory")
#define CP_WAIT0()           asm volatile("cp.async.wait_group 0;" ::: "memory")

__device__ __forceinline__ uint2 f4_to_h4(float4 v) {
    __half2 h0 = __float22half2_rn(make_float2(v.x, v.y));
    __half2 h1 = __float22half2_rn(make_float2(v.z, v.w));
    uint2 r;
    r.x = *reinterpret_cast<uint32_t*>(&h0);
    r.y = *reinterpret_cast<uint32_t*>(&h1);
    return r;
}
__device__ __forceinline__ float4 h4_to_f4(uint2 u) {
    __half2 h0 = *reinterpret_cast<__half2*>(&u.x);
    __half2 h1 = *reinterpret_cast<__half2*>(&u.y);
    float2 a = __half22float2(h0), b = __half22float2(h1);
    return make_float4(a.x, a.y, b.x, b.y);
}

#define STAGE_BYTES 32768u    // A 16KB (128x64 fp16) + B 16KB (128x64 fp16)
#define SM_TOTAL (3 * STAGE_BYTES)   // 96KB/CTA -> 2 CTAs/SM

// ---------------------------------------------------------------------------
// Merged prep: frames f32->fp16, weights pack+transpose, t_emb-folded bias.
// ---------------------------------------------------------------------------
#define NBLK_FRAMES 64512     // ROWS*CDIM/4/256
#define NBLK_WT     1024      // (NQKV*CDIM + CDIM*CDIM)/256
#define NBLK_BIAS   21        // ceil(T_*NQKV/256)

__global__ void prep_all_kernel(const float* __restrict__ frames,
                                const float* __restrict__ te,
                                const float* __restrict__ Wq,
                                const float* __restrict__ bq,
                                const float* __restrict__ Wk,
                                const float* __restrict__ bk,
                                const float* __restrict__ Wv,
                                const float* __restrict__ bv,
                                const float* __restrict__ Wo) {
    const int bid = blockIdx.x;
    if (bid < NBLK_FRAMES) {
        size_t i = (size_t)bid * 256 + threadIdx.x;     // float4 slot
        const float4 v = reinterpret_cast<const float4*>(frames)[i];
        reinterpret_cast<uint2*>(g_a_h)[i] = f4_to_h4(v);
    } else if (bid < NBLK_FRAMES + NBLK_WT) {
        int i = (bid - NBLK_FRAMES) * 256 + threadIdx.x;
        if (i < NQKV * CDIM) {
            int n = i / CDIM, c = i % CDIM;
            float v;
            if (n < 256)      v = Wq[c * 256 + n];
            else if (n < 512) v = Wk[c * 256 + (n - 256)];
            else              v = Wv[c * 256 + (n - 512)];
            g_wbt_h[i] = __float2half_rn(v);
        } else {
            int j = i - NQKV * CDIM;
            int co = j / CDIM, nd = j % CDIM;
            g_wot_h[j] = __float2half_rn(Wo[nd * 256 + co]);
        }
    } else {
        int i = (bid - NBLK_FRAMES - NBLK_WT) * 256 + threadIdx.x;
        if (i >= T_ * NQKV) return;
        int t = i / NQKV, n = i % NQKV;
        float r;
        if (n < 512) {
            const float* W = (n < 256) ? Wq : Wk;
            int nn = n & 255;
            float acc = (n < 256) ? bq[nn] : bk[nn];
            for (int c = 0; c < CDIM; c++) acc += te[t * CDIM + c] * W[c * 256 + nn];
            r = acc;
        } else {
            r = bv[n - 512];
        }
        g_bias[i] = r;
    }
}

// ---------------------------------------------------------------------------
// fp16 mma.sync GEMM (R8-proven): C[row][n] = A[row][k] * Bt[n][k] + bias
// CTA 128(M) x 128(N), K=256 in 4 chunks of 64, 3-stage cp.async pipeline,
// next-stage issued BEFORE compute. 8 warps, warp tile 32x64.
// __launch_bounds__(256,2): 2 CTAs/SM.
// ---------------------------------------------------------------------------
template<int NW, int TSTRIDE, bool OUT_HALF>
__global__ __launch_bounds__(256, 2)
void gemm_h_kernel(const __half* __restrict__ A,
                   const __half* __restrict__ Bt,
                   const float* __restrict__ bias,
                   void* __restrict__ Cout) {
    extern __shared__ __align__(128) char smem[];
    const uint32_t sb = smem_u32(smem);

    const int tid  = threadIdx.x;
    const int lane = tid & 31, wid = tid >> 5;
    const int wm = wid >> 1;          // 0..3 : rows wm*32
    const int wn = wid & 1;           // 0..1 : cols wn*64
    const int row0 = blockIdx.y * 128;
    const int col0 = blockIdx.x * 128;

    const uint32_t fxor  = (uint32_t)(lane & 7) << 4;
    const uint32_t a_row = (uint32_t)(wm * 32 + (lane & 15)) * 128;
    const uint32_t ahalf = (uint32_t)(lane >> 4) * 16;
    const uint32_t b_row = (uint32_t)(wn * 64 + (lane & 7) + ((lane >> 4) << 3)) * 128;
    const uint32_t bhalf = (uint32_t)((lane >> 3) & 1) * 16;

    auto stageA = [&](int kc, uint32_t nb) {
        #pragma unroll
        for (int i = 0; i < 4; i++) {
            int g = tid + i * 256;
            int r = g >> 3, c16 = g & 7;
            uint32_t dst = nb + (uint32_t)r * 128 + (((uint32_t)c16 * 16) ^ (((uint32_t)(r & 7)) << 4));
            CP_ASYNC16(dst, A + (size_t)(row0 + r) * CDIM + kc * 64 + c16 * 8);
        }
    };
    auto stageB = [&](int kc, uint32_t nb) {
        #pragma unroll
        for (int i = 0; i < 4; i++) {
            int g = tid + i * 256;
            int r = g >> 3, c16 = g & 7;
            uint32_t dst = nb + 16384u + (uint32_t)r * 128 + (((uint32_t)c16 * 16) ^ (((uint32_t)(r & 7)) << 4));
            CP_ASYNC16(dst, Bt + (size_t)(col0 + r) * CDIM + kc * 64 + c16 * 8);
        }
    };

    stageA(0, sb);               stageB(0, sb);               CP_COMMIT();
    stageA(1, sb + STAGE_BYTES); stageB(1, sb + STAGE_BYTES); CP_COMMIT();

    float acc[2][8][4];
    #pragma unroll
    for (int mt = 0; mt < 2; mt++)
        #pragma unroll
        for (int nt = 0; nt < 8; nt++)
            #pragma unroll
            for (int e = 0; e < 4; e++) acc[mt][nt][e] = 0.0f;

    #pragma unroll 1
    for (int kc = 0; kc < 4; kc++) {
        const uint32_t sbase = sb + (uint32_t)(kc % 3) * STAGE_BYTES;
        if (kc == 3) { CP_WAIT0(); } else { CP_WAIT1(); }
        __syncthreads();

        if (kc < 2) {
            const uint32_t nb = sb + (uint32_t)((kc + 2) % 3) * STAGE_BYTES;
            stageA(kc + 2, nb);
            stageB(kc + 2, nb);
            CP_COMMIT();
        }

        #pragma unroll
        for (int ks = 0; ks < 4; ks++) {
            uint32_t af[2][4];
            #pragma unroll
            for (int mt = 0; mt < 2; mt++)
                ldsm4(af[mt], sbase + a_row + (uint32_t)mt * 2048 + ((ahalf + ks * 32) ^ fxor));
            uint32_t bf[4][4];
            #pragma unroll
            for (int np = 0; np < 4; np++)
                ldsm4(bf[np], sbase + 16384u + b_row + (uint32_t)np * 2048 + ((bhalf + ks * 32) ^ fxor));
            #pragma unroll
            for (int mt = 0; mt < 2; mt++)
                #pragma unroll
                for (int nt = 0; nt < 8; nt++)
                    mma_f16(acc[mt][nt], af[mt], &bf[nt >> 1][(nt & 1) * 2]);
        }
    }
    __syncthreads();

    float* Cs = reinterpret_cast<float*>(smem);    // [128][132] = 67.6KB
    #pragma unroll
    for (int mt = 0; mt < 2; mt++) {
        const int r0 = wm * 32 + mt * 16 + (lane >> 2);
        #pragma unroll
        for (int nt = 0; nt < 8; nt++) {
            const int c0 = wn * 64 + nt * 8 + (lane & 3) * 2;
            *reinterpret_cast<float2*>(Cs + r0 * 132 + c0)       = make_float2(acc[mt][nt][0], acc[mt][nt][1]);
            *reinterpret_cast<float2*>(Cs + (r0 + 8) * 132 + c0) = make_float2(acc[mt][nt][2], acc[mt][nt][3]);
        }
    }
    __syncthreads();

    const int t = TSTRIDE ? (blockIdx.y / 288) : 0;
    #pragma unroll
    for (int i = 0; i < 16; i++) {
        int id = tid + i * 256;                    // 4096 float4 slots
        int r = id >> 5, c = (id & 31) * 4;
        float4 v = *reinterpret_cast<const float4*>(Cs + r * 132 + c);
        int n = col0 + c;
        const float4 b4 = *reinterpret_cast<const float4*>(bias + t * TSTRIDE + n);
        v.x += b4.x; v.y += b4.y; v.z += b4.z; v.w += b4.w;
        if (OUT_HALF) {
            *reinterpret_cast<uint2*>(reinterpret_cast<__half*>(Cout) + (size_t)(row0 + r) * NW + n) = f4_to_h4(v);
        } else {
            *reinterpret_cast<float4*>(reinterpret_cast<float*>(Cout) + (size_t)(row0 + r) * NW + n) = v;
        }
    }
}

// ---------------------------------------------------------------------------
// Attention over T=7 per (token, 4-head group), fp16 in / fp16 out.
// K and V stay PACKED fp16 in registers (uint2), converted once per t in
// t-outer loops: peak live regs drop ~80 -> ~65 => higher occupancy for this
// latency-bound kernel. Summation order is identical to the previous version
// (for fixed qt, t ascends 0..6 in both) => bitwise-identical results.
// ---------------------------------------------------------------------------
__global__ void attn_kernel() {
    const int gw = (blockIdx.x * blockDim.x + threadIdx.x) >> 5;
    const int lane = threadIdx.x & 31;
    const int s = gw >> 1;
    const int half = gw & 1;
    const int hg = lane >> 3, dg = lane & 7;
    const int col = (half * 4 + hg) * 32 + dg * 4;

    float4 q[7];
    uint2 kp[7], vp[7];
    #pragma unroll
    for (int t = 0; t < 7; t++) {
        const __half* base = g_qkv_h + (size_t)(t * NTOK + s) * NQKV;
        q[t]  = h4_to_f4(*reinterpret_cast<const uint2*>(base + col));
        kp[t] = *reinterpret_cast<const uint2*>(base + 256 + col);
        vp[t] = *reinterpret_cast<const uint2*>(base + 512 + col);
    }

    const float scale = 0.17677669529663687f;  // 1/sqrt(32)
    float e[7] = {0.f, 0.f, 0.f, 0.f, 0.f, 0.f, 0.f};
    #pragma unroll
    for (int t = 0; t < 7; t++) {
        const float4 kf = h4_to_f4(kp[t]);
        #pragma unroll
        for (int qt = 0; qt < 7; qt++) {
            float d = q[qt].x * kf.x + q[qt].y * kf.y
                    + q[qt].z * kf.z + q[qt].w * kf.w;
            d += __shfl_xor_sync(0xffffffffu, d, 1);
            d += __shfl_xor_sync(0xffffffffu, d, 2);
            d += __shfl_xor_sync(0xffffffffu, d, 4);
            const int p = qt * 7 + t;
            if ((p & 7) == dg) e[p >> 3] = __expf(d * scale);
        }
    }

    float4 ctx[7];
    float den[7];
    #pragma unroll
    for (int qt = 0; qt < 7; qt++) { ctx[qt] = make_float4(0, 0, 0, 0); den[qt] = 0.f; }
    #pragma unroll
    for (int t = 0; t < 7; t++) {
        const float4 vf = h4_to_f4(vp[t]);
        #pragma unroll
        for (int qt = 0; qt < 7; qt++) {
            const int p = qt * 7 + t;
            float eb = __shfl_sync(0xffffffffu, e[p >> 3], p & 7, 8);
            den[qt] += eb;
            ctx[qt].x += eb * vf.x;
            ctx[qt].y += eb * vf.y;
            ctx[qt].z += eb * vf.z;
            ctx[qt].w += eb * vf.w;
        }
    }
    #pragma unroll
    for (int qt = 0; qt < 7; qt++) {
        const float r = 1.0f / den[qt];
        float4 o = make_float4(ctx[qt].x * r, ctx[qt].y * r, ctx[qt].z * r, ctx[qt].w * r);
        *reinterpret_cast<uint2*>(g_ctx_h + (size_t)(qt * NTOK + s) * CDIM + col) = f4_to_h4(o);
    }
}

// ---------------------------------------------------------------------------
extern "C" void kernel_launch(void* const* d_in, const int* /*in_sizes*/, int /*n_in*/,
                              void* d_out, int /*out_size*/) {
    const float* frames = (const float*)d_in[0];
    const float* temb   = (const float*)d_in[1];
    const float* Wq     = (const float*)d_in[2];
    const float* bq     = (const float*)d_in[3];
    const float* Wk     = (const float*)d_in[4];
    const float* bk     = (const float*)d_in[5];
    const float* Wv     = (const float*)d_in[6];
    const float* bv     = (const float*)d_in[7];
    const float* Wo     = (const float*)d_in[8];
    const float* bo     = (const float*)d_in[9];
    float* out = (float*)d_out;

    void *p_ah, *p_qkv, *p_ctx, *p_wbt, *p_wot, *p_bias;
    cudaGetSymbolAddress(&p_ah,   g_a_h);
    cudaGetSymbolAddress(&p_qkv,  g_qkv_h);
    cudaGetSymbolAddress(&p_ctx,  g_ctx_h);
    cudaGetSymbolAddress(&p_wbt,  g_wbt_h);
    cudaGetSymbolAddress(&p_wot,  g_wot_h);
    cudaGetSymbolAddress(&p_bias, g_bias);

    cudaFuncSetAttribute(gemm_h_kernel<NQKV, NQKV, true>,
                         cudaFuncAttributeMaxDynamicSharedMemorySize, SM_TOTAL);
    cudaFuncSetAttribute(gemm_h_kernel<CDIM, 0, false>,
                         cudaFuncAttributeMaxDynamicSharedMemorySize, SM_TOTAL);

    // Single prep launch: frames->fp16, weight pack, bias fold
    prep_all_kernel<<<NBLK_FRAMES + NBLK_WT + NBLK_BIAS, 256>>>(
        frames, temb, Wq, bq, Wk, bk, Wv, bv, Wo);

    // QKV projection: [258048 x 256] @ [256 x 768] + bias[t]  -> fp16 qkv
    gemm_h_kernel<NQKV, NQKV, true><<<dim3(6, ROWS / 128), 256, SM_TOTAL>>>(
        (const __half*)p_ah, (const __half*)p_wbt, (const float*)p_bias, p_qkv);

    // Attention (fp16 -> fp16)
    attn_kernel<<<(NTOK * 2 * 32) / 256, 256>>>();

    // Output projection: [258048 x 256] @ [256 x 256] + bo -> f32 out
    gemm_h_kernel<CDIM, 0, false><<<dim3(2, ROWS / 128), 256, SM_TOTAL>>>(
        (const __half*)p_ctx, (const __half*)p_wot, bo, out);
}

// round 16
// speedup vs baseline: 2.6229x; 1.0029x over previous
#include <cuda_runtime.h>
#include <cuda_fp16.h>
#include <cstdint>

#define T_ 7
#define NTOK 36864            // B*H*W
#define ROWS (T_ * NTOK)      // 258048
#define CDIM 256
#define NQKV 768
#define NCTA 296              // 2 CTAs x 148 SMs

// Scratch (device globals — no allocation allowed)
__device__ __half g_a_h[(size_t)ROWS * CDIM];    // frames, fp16
__device__ __half g_qkv_h[(size_t)ROWS * NQKV];  // [t*NTOK+s][q|k|v], fp16
__device__ __half g_ctx_h[(size_t)ROWS * CDIM];  // attn out, fp16
__device__ __half g_wbt_h[NQKV * CDIM];          // [n][k], fp16
__device__ __half g_wot_h[CDIM * CDIM];          // [c][nd], fp16
__device__ float  g_bias[T_ * NQKV];

// ---------------------------------------------------------------------------
// Portable PTX helpers (compute_103 virtual arch — no tcgen05/TMA-tensor)
// ---------------------------------------------------------------------------
__device__ __forceinline__ uint32_t smem_u32(const void* p) {
    uint32_t a;
    asm("{ .reg .u64 t; cvta.to.shared.u64 t, %1; cvt.u32.u64 %0, t; }" : "=r"(a) : "l"(p));
    return a;
}
__device__ __forceinline__ void ldsm4(uint32_t* r, uint32_t addr) {
    asm volatile("ldmatrix.sync.aligned.m8n8.x4.shared.b16 {%0,%1,%2,%3}, [%4];"
        : "=r"(r[0]), "=r"(r[1]), "=r"(r[2]), "=r"(r[3]) : "r"(addr));
}
__device__ __forceinline__ void mma_f16(float* d, const uint32_t* a, const uint32_t* b) {
    asm volatile("mma.sync.aligned.m16n8k16.row.col.f32.f16.f16.f32 "
        "{%0,%1,%2,%3}, {%4,%5,%6,%7}, {%8,%9}, {%0,%1,%2,%3};"
        : "+f"(d[0]), "+f"(d[1]), "+f"(d[2]), "+f"(d[3])
        : "r"(a[0]), "r"(a[1]), "r"(a[2]), "r"(a[3]), "r"(b[0]), "r"(b[1]));
}
#define CP_ASYNC16(dst, src) asm volatile("cp.async.cg.shared.global [%0], [%1], 16;" :: "r"(dst), "l"(src))
#define CP_COMMIT()          asm volatile("cp.async.commit_group;" ::: "memory")
#define CP_WAIT1()           asm volatile("cp.async.wait_group 1;" ::: "memory")

__device__ __forceinline__ uint2 f4_to_h4(float4 v) {
    __half2 h0 = __float22half2_rn(make_float2(v.x, v.y));
    __half2 h1 = __float22half2_rn(make_float2(v.z, v.w));
    uint2 r;
    r.x = *reinterpret_cast<uint32_t*>(&h0);
    r.y = *reinterpret_cast<uint32_t*>(&h1);
    return r;
}
__device__ __forceinline__ float4 h4_to_f4(uint2 u) {
    __half2 h0 = *reinterpret_cast<__half2*>(&u.x);
    __half2 h1 = *reinterpret_cast<__half2*>(&u.y);
    float2 a = __half22float2(h0), b = __half22float2(h1);
    return make_float4(a.x, a.y, b.x, b.y);
}

#define STAGE_BYTES 32768u    // A 16KB (128x64 fp16) + B 16KB (128x64 fp16)
#define SM_TOTAL (3 * STAGE_BYTES)   // 96KB/CTA -> 2 CTAs/SM

// ---------------------------------------------------------------------------
// Merged prep: frames f32->fp16, weights pack+transpose, t_emb-folded bias.
// ---------------------------------------------------------------------------
#define NBLK_FRAMES 64512     // ROWS*CDIM/4/256
#define NBLK_WT     1024      // (NQKV*CDIM + CDIM*CDIM)/256
#define NBLK_BIAS   21        // ceil(T_*NQKV/256)

__global__ void prep_all_kernel(const float* __restrict__ frames,
                                const float* __restrict__ te,
                                const float* __restrict__ Wq,
                                const float* __restrict__ bq,
                                const float* __restrict__ Wk,
                                const float* __restrict__ bk,
                                const float* __restrict__ Wv,
                                const float* __restrict__ bv,
                                const float* __restrict__ Wo) {
    const int bid = blockIdx.x;
    if (bid < NBLK_FRAMES) {
        size_t i = (size_t)bid * 256 + threadIdx.x;     // float4 slot
        const float4 v = reinterpret_cast<const float4*>(frames)[i];
        reinterpret_cast<uint2*>(g_a_h)[i] = f4_to_h4(v);
    } else if (bid < NBLK_FRAMES + NBLK_WT) {
        int i = (bid - NBLK_FRAMES) * 256 + threadIdx.x;
        if (i < NQKV * CDIM) {
            int n = i / CDIM, c = i % CDIM;
            float v;
            if (n < 256)      v = Wq[c * 256 + n];
            else if (n < 512) v = Wk[c * 256 + (n - 256)];
            else              v = Wv[c * 256 + (n - 512)];
            g_wbt_h[i] = __float2half_rn(v);
        } else {
            int j = i - NQKV * CDIM;
            int co = j / CDIM, nd = j % CDIM;
            g_wot_h[j] = __float2half_rn(Wo[nd * 256 + co]);
        }
    } else {
        int i = (bid - NBLK_FRAMES - NBLK_WT) * 256 + threadIdx.x;
        if (i >= T_ * NQKV) return;
        int t = i / NQKV, n = i % NQKV;
        float r;
        if (n < 512) {
            const float* W = (n < 256) ? Wq : Wk;
            int nn = n & 255;
            float acc = (n < 256) ? bq[nn] : bk[nn];
            for (int c = 0; c < CDIM; c++) acc += te[t * CDIM + c] * W[c * 256 + nn];
            r = acc;
        } else {
            r = bv[n - 512];
        }
        g_bias[i] = r;
    }
}

// ---------------------------------------------------------------------------
// Persistent fp16 mma.sync GEMM: C[row][n] = A[row][k] * Bt[n][k] + bias
// 296 CTAs; CTA c runs tiles tau = c, c+296, ... (128x128 each).
// Continuous 3-buffer ring (fill paid once per CTA; next tile's chunks are in
// flight during the epilogue). Epilogue:
//   OUT_HALF: acc+bias -> fp16 in regs; 2 passes of 64 rows staged as
//             [64][136] fp16 (17.4KB) in the freed ring slot.
//             Store loop: 1024 slots = 64 rows (id>>4) x 16 uint4 (id&15).
//   f32     : 4 passes of 32 rows staged as [32][132] f32 (R12-proven).
// 8 warps, warp tile 32x64, __launch_bounds__(256,2).
// ---------------------------------------------------------------------------
template<int NB, int TSTRIDE, bool OUT_HALF>
__global__ __launch_bounds__(256, 2)
void gemm_persist_kernel(const __half* __restrict__ A,
                         const __half* __restrict__ Bt,
                         const float* __restrict__ bias,
                         void* __restrict__ Cout) {
    extern __shared__ __align__(128) char smem[];
    const uint32_t sb = smem_u32(smem);
    const int NWIDTH = NB * 128;
    const int ntiles = NB * (ROWS / 128);

    const int tid  = threadIdx.x;
    const int lane = tid & 31, wid = tid >> 5;
    const int wm = wid >> 1;          // 0..3 : rows wm*32
    const int wn = wid & 1;           // 0..1 : cols wn*64
    const int cblk = blockIdx.x;

    const uint32_t fxor  = (uint32_t)(lane & 7) << 4;
    const uint32_t a_row = (uint32_t)(wm * 32 + (lane & 15)) * 128;
    const uint32_t ahalf = (uint32_t)(lane >> 4) * 16;
    const uint32_t b_row = (uint32_t)(wn * 64 + (lane & 7) + ((lane >> 4) << 3)) * 128;
    const uint32_t bhalf = (uint32_t)((lane >> 3) & 1) * 16;

    auto stageG = [&](int gl) {
        const int tt = cblk + (gl >> 2) * NCTA;
        if (tt < ntiles) {
            const int kc = gl & 3;
            const int r0 = (tt / NB) * 128;
            const int c0 = (tt % NB) * 128;
            const uint32_t nb = sb + (uint32_t)(gl % 3) * STAGE_BYTES;
            #pragma unroll
            for (int i = 0; i < 4; i++) {
                int g = tid + i * 256;
                int r = g >> 3, c16 = g & 7;
                uint32_t dst = nb + (uint32_t)r * 128 + (((uint32_t)c16 * 16) ^ (((uint32_t)(r & 7)) << 4));
                CP_ASYNC16(dst, A + (size_t)(r0 + r) * CDIM + kc * 64 + c16 * 8);
            }
            #pragma unroll
            for (int i = 0; i < 4; i++) {
                int g = tid + i * 256;
                int r = g >> 3, c16 = g & 7;
                uint32_t dst = nb + 16384u + (uint32_t)r * 128 + (((uint32_t)c16 * 16) ^ (((uint32_t)(r & 7)) << 4));
                CP_ASYNC16(dst, Bt + (size_t)(c0 + r) * CDIM + kc * 64 + c16 * 8);
            }
        }
        CP_COMMIT();   // commit even when empty: uniform group accounting
    };

    stageG(0);
    stageG(1);

    int gl = 0;
    #pragma unroll 1
    for (int tau = cblk; tau < ntiles; tau += NCTA) {
        const int rowblk = tau / NB;
        const int row0 = rowblk * 128;
        const int col0 = (tau % NB) * 128;

        float acc[2][8][4];
        #pragma unroll
        for (int mt = 0; mt < 2; mt++)
            #pragma unroll
            for (int nt = 0; nt < 8; nt++)
                #pragma unroll
                for (int e = 0; e < 4; e++) acc[mt][nt][e] = 0.0f;

        #pragma unroll 1
        for (int kc = 0; kc < 4; kc++, gl++) {
            const uint32_t base = sb + (uint32_t)(gl % 3) * STAGE_BYTES;
            CP_WAIT1();
            __syncthreads();
            stageG(gl + 2);   // next chunks (crosses into next tile at kc=2,3)

            #pragma unroll
            for (int ks = 0; ks < 4; ks++) {
                uint32_t af[2][4];
                #pragma unroll
                for (int mt = 0; mt < 2; mt++)
                    ldsm4(af[mt], base + a_row + (uint32_t)mt * 2048 + ((ahalf + ks * 32) ^ fxor));
                uint32_t bf[4][4];
                #pragma unroll
                for (int np = 0; np < 4; np++)
                    ldsm4(bf[np], base + 16384u + b_row + (uint32_t)np * 2048 + ((bhalf + ks * 32) ^ fxor));
                #pragma unroll
                for (int mt = 0; mt < 2; mt++)
                    #pragma unroll
                    for (int nt = 0; nt < 8; nt++)
                        mma_f16(acc[mt][nt], af[mt], &bf[nt >> 1][(nt & 1) * 2]);
            }
        }
        __syncthreads();   // all reads of the freed buffer done

        // ---- epilogue (freed ring slot (gl+2)%3; next tile's loads in flight) ----
        char* Fs = smem + (size_t)((gl + 2) % 3) * STAGE_BYTES;
        const int t = TSTRIDE ? (rowblk / 288) : 0;
        float2 br[8];
        #pragma unroll
        for (int nt = 0; nt < 8; nt++)
            br[nt] = *reinterpret_cast<const float2*>(
                bias + t * TSTRIDE + col0 + wn * 64 + nt * 8 + (lane & 3) * 2);

        if (OUT_HALF) {
            // 2 passes of 64 rows, [64][136] fp16 = 17.4KB
            __half* Hs = reinterpret_cast<__half*>(Fs);
            __half* outp = reinterpret_cast<__half*>(Cout);
            #pragma unroll 1
            for (int p = 0; p < 2; p++) {
                if ((wm >> 1) == p) {
                    const int lrb = (wm & 1) * 32;
                    #pragma unroll
                    for (int mt = 0; mt < 2; mt++) {
                        const int lr = lrb + mt * 16 + (lane >> 2);
                        #pragma unroll
                        for (int nt = 0; nt < 8; nt++) {
                            const int c0 = wn * 64 + nt * 8 + (lane & 3) * 2;
                            __half2 v0 = __float22half2_rn(make_float2(acc[mt][nt][0] + br[nt].x,
                                                                       acc[mt][nt][1] + br[nt].y));
                            __half2 v1 = __float22half2_rn(make_float2(acc[mt][nt][2] + br[nt].x,
                                                                       acc[mt][nt][3] + br[nt].y));
                            *reinterpret_cast<__half2*>(Hs + lr * 136 + c0)       = v0;
                            *reinterpret_cast<__half2*>(Hs + (lr + 8) * 136 + c0) = v1;
                        }
                    }
                }
                __syncthreads();
                #pragma unroll
                for (int i = 0; i < 4; i++) {
                    int id = tid + i * 256;          // 1024 slots: 64 rows x 16 uint4
                    int r = id >> 4, c8 = id & 15;
                    uint4 v = *reinterpret_cast<const uint4*>(Hs + r * 136 + c8 * 8);
                    *reinterpret_cast<uint4*>(outp + (size_t)(row0 + p * 64 + r) * NWIDTH + col0 + c8 * 8) = v;
                }
                __syncthreads();
            }
        } else {
            // 4 passes of 32 rows, [32][132] f32 (R12-proven)
            float* Cs = reinterpret_cast<float*>(Fs);
            float* outp = reinterpret_cast<float*>(Cout);
            #pragma unroll 1
            for (int p = 0; p < 4; p++) {
                if (wm == p) {
                    #pragma unroll
                    for (int mt = 0; mt < 2; mt++) {
                        const int r0 = mt * 16 + (lane >> 2);
                        #pragma unroll
                        for (int nt = 0; nt < 8; nt++) {
                            const int c0 = wn * 64 + nt * 8 + (lane & 3) * 2;
                            *reinterpret_cast<float2*>(Cs + r0 * 132 + c0) =
                                make_float2(acc[mt][nt][0] + br[nt].x, acc[mt][nt][1] + br[nt].y);
                            *reinterpret_cast<float2*>(Cs + (r0 + 8) * 132 + c0) =
                                make_float2(acc[mt][nt][2] + br[nt].x, acc[mt][nt][3] + br[nt].y);
                        }
                    }
                }
                __syncthreads();
                #pragma unroll
                for (int i = 0; i < 4; i++) {
                    int id = tid + i * 256;          // 1024 float4: 32 rows x 32
                    int r = id >> 5, c = (id & 31) * 4;
                    float4 v = *reinterpret_cast<const float4*>(Cs + r * 132 + c);
                    *reinterpret_cast<float4*>(outp + (size_t)(row0 + p * 32 + r) * NWIDTH + col0 + c) = v;
                }
                __syncthreads();
            }
        }
    }
}

// ---------------------------------------------------------------------------
// Attention over T=7 per (token, 4-head group), fp16 in / fp16 out.
// K/V stay packed fp16 (uint2), converted once per t (R14-proven, ~65 regs).
// ---------------------------------------------------------------------------
__global__ void attn_kernel() {
    const int gw = (blockIdx.x * blockDim.x + threadIdx.x) >> 5;
    const int lane = threadIdx.x & 31;
    const int s = gw >> 1;
    const int half = gw & 1;
    const int hg = lane >> 3, dg = lane & 7;
    const int col = (half * 4 + hg) * 32 + dg * 4;

    float4 q[7];
    uint2 kp[7], vp[7];
    #pragma unroll
    for (int t = 0; t < 7; t++) {
        const __half* base = g_qkv_h + (size_t)(t * NTOK + s) * NQKV;
        q[t]  = h4_to_f4(*reinterpret_cast<const uint2*>(base + col));
        kp[t] = *reinterpret_cast<const uint2*>(base + 256 + col);
        vp[t] = *reinterpret_cast<const uint2*>(base + 512 + col);
    }

    const float scale = 0.17677669529663687f;  // 1/sqrt(32)
    float e[7] = {0.f, 0.f, 0.f, 0.f, 0.f, 0.f, 0.f};
    #pragma unroll
    for (int t = 0; t < 7; t++) {
        const float4 kf = h4_to_f4(kp[t]);
        #pragma unroll
        for (int qt = 0; qt < 7; qt++) {
            float d = q[qt].x * kf.x + q[qt].y * kf.y
                    + q[qt].z * kf.z + q[qt].w * kf.w;
            d += __shfl_xor_sync(0xffffffffu, d, 1);
            d += __shfl_xor_sync(0xffffffffu, d, 2);
            d += __shfl_xor_sync(0xffffffffu, d, 4);
            const int p = qt * 7 + t;
            if ((p & 7) == dg) e[p >> 3] = __expf(d * scale);
        }
    }

    float4 ctx[7];
    float den[7];
    #pragma unroll
    for (int qt = 0; qt < 7; qt++) { ctx[qt] = make_float4(0, 0, 0, 0); den[qt] = 0.f; }
    #pragma unroll
    for (int t = 0; t < 7; t++) {
        const float4 vf = h4_to_f4(vp[t]);
        #pragma unroll
        for (int qt = 0; qt < 7; qt++) {
            const int p = qt * 7 + t;
            float eb = __shfl_sync(0xffffffffu, e[p >> 3], p & 7, 8);
            den[qt] += eb;
            ctx[qt].x += eb * vf.x;
            ctx[qt].y += eb * vf.y;
            ctx[qt].z += eb * vf.z;
            ctx[qt].w += eb * vf.w;
        }
    }
    #pragma unroll
    for (int qt = 0; qt < 7; qt++) {
        const float r = 1.0f / den[qt];
        float4 o = make_float4(ctx[qt].x * r, ctx[qt].y * r, ctx[qt].z * r, ctx[qt].w * r);
        *reinterpret_cast<uint2*>(g_ctx_h + (size_t)(qt * NTOK + s) * CDIM + col) = f4_to_h4(o);
    }
}

// ---------------------------------------------------------------------------
extern "C" void kernel_launch(void* const* d_in, const int* /*in_sizes*/, int /*n_in*/,
                              void* d_out, int /*out_size*/) {
    const float* frames = (const float*)d_in[0];
    const float* temb   = (const float*)d_in[1];
    const float* Wq     = (const float*)d_in[2];
    const float* bq     = (const float*)d_in[3];
    const float* Wk     = (const float*)d_in[4];
    const float* bk     = (const float*)d_in[5];
    const float* Wv     = (const float*)d_in[6];
    const float* bv     = (const float*)d_in[7];
    const float* Wo     = (const float*)d_in[8];
    const float* bo     = (const float*)d_in[9];
    float* out = (float*)d_out;

    void *p_ah, *p_qkv, *p_ctx, *p_wbt, *p_wot, *p_bias;
    cudaGetSymbolAddress(&p_ah,   g_a_h);
    cudaGetSymbolAddress(&p_qkv,  g_qkv_h);
    cudaGetSymbolAddress(&p_ctx,  g_ctx_h);
    cudaGetSymbolAddress(&p_wbt,  g_wbt_h);
    cudaGetSymbolAddress(&p_wot,  g_wot_h);
    cudaGetSymbolAddress(&p_bias, g_bias);

    cudaFuncSetAttribute(gemm_persist_kernel<6, NQKV, true>,
                         cudaFuncAttributeMaxDynamicSharedMemorySize, SM_TOTAL);
    cudaFuncSetAttribute(gemm_persist_kernel<2, 0, false>,
                         cudaFuncAttributeMaxDynamicSharedMemorySize, SM_TOTAL);

    // Single prep launch: frames->fp16, weight pack, bias fold
    prep_all_kernel<<<NBLK_FRAMES + NBLK_WT + NBLK_BIAS, 256>>>(
        frames, temb, Wq, bq, Wk, bk, Wv, bv, Wo);

    // QKV projection (persistent): [258048 x 256] @ [256 x 768] + bias[t] -> fp16
    gemm_persist_kernel<6, NQKV, true><<<NCTA, 256, SM_TOTAL>>>(
        (const __half*)p_ah, (const __half*)p_wbt, (const float*)p_bias, (void*)p_qkv);

    // Attention (fp16 -> fp16)
    attn_kernel<<<(NTOK * 2 * 32) / 256, 256>>>();

    // Output projection (persistent): [258048 x 256] @ [256 x 256] + bo -> f32
    gemm_persist_kernel<2, 0, false><<<NCTA, 256, SM_TOTAL>>>(
        (const __half*)p_ctx, (const __half*)p_wot, bo, (void*)out);
}